// round 11
// baseline (speedup 1.0000x reference)
#include <cuda_runtime.h>
#include <cuda_fp16.h>
#include <math.h>
#include <stdint.h>

// ----------------------------------------------------------------------------
// LlamaAttention + H2O mask. fp16 tensor-core GEMMs (m16n8k16):
//   - mask-critical path (Wq, Wk, QK^T): fp16x2 3-product staged split with
//     PRE-PACKED big/small operands (split hoisted out of the GEMM fill;
//     bitwise-identical math to the in-GEMM split).
//   - Output-0-only path (Wv, attn*V, Wo): plain fp16.
// B=1, S=2048, HID=4096, NH=32, NKV=8, HD=128, GROUPS=4, HB=RB=204
// ----------------------------------------------------------------------------

#define S_LEN   2048
#define HID     4096
#define NH      32
#define NKV     8
#define HD      128
#define HB      204
#define RB      204
#define SEL     (S_LEN - RB)   // 1844

__device__ float g_Q [S_LEN * HID];
__device__ float g_K [S_LEN * NKV * HD];
__device__ float g_V [S_LEN * NKV * HD];
__device__ float g_S [(size_t)NH * S_LEN * S_LEN];
__device__ float g_O [S_LEN * HID];
__device__ float g_CS[NH * S_LEN];

// packed big/small fp16x2 operand arrays (u32 = one k-pair)
__device__ uint32_t g_Hb [S_LEN * HID / 2];
__device__ uint32_t g_Hs [S_LEN * HID / 2];
__device__ uint32_t g_Wqb[HID * HID / 2];
__device__ uint32_t g_Wqs[HID * HID / 2];
__device__ uint32_t g_Wkb[NKV * HD * HID / 2];
__device__ uint32_t g_Wks[NKV * HD * HID / 2];
__device__ uint32_t g_Qb [S_LEN * HID / 2];
__device__ uint32_t g_Qs [S_LEN * HID / 2];
__device__ uint32_t g_Kb [S_LEN * NKV * HD / 2];
__device__ uint32_t g_Ks [S_LEN * NKV * HD / 2];

// pack two fp32 (consecutive k) into one fp16x2 register (low = even k)
__device__ __forceinline__ uint32_t f2h2(float lo, float hi) {
    __half2 h = __floats2half2_rn(lo, hi);
    return *reinterpret_cast<uint32_t*>(&h);
}

// split-pack: big pair + small (residual) pair
__device__ __forceinline__ void split_pack(float x0, float x1,
                                           uint32_t& bp, uint32_t& sp) {
    __half b0 = __float2half_rn(x0);
    __half b1 = __float2half_rn(x1);
    float r0 = x0 - __half2float(b0);
    float r1 = x1 - __half2float(b1);
    __half2 bb = __halves2half2(b0, b1);
    __half2 ss = __halves2half2(__float2half_rn(r0), __float2half_rn(r1));
    bp = *reinterpret_cast<uint32_t*>(&bb);
    sp = *reinterpret_cast<uint32_t*>(&ss);
}

// D += A*B  (fp16 m16n8k16, fp32 accumulate)
__device__ __forceinline__ void mma_f16(float* c, const uint32_t* a, const uint32_t* b) {
    asm volatile(
        "mma.sync.aligned.m16n8k16.row.col.f32.f16.f16.f32 "
        "{%0,%1,%2,%3}, {%4,%5,%6,%7}, {%8,%9}, {%0,%1,%2,%3};"
        : "+f"(c[0]), "+f"(c[1]), "+f"(c[2]), "+f"(c[3])
        : "r"(a[0]), "r"(a[1]), "r"(a[2]), "r"(a[3]), "r"(b[0]), "r"(b[1]));
}

// D = A*B + 0 (fresh accumulation chain)
__device__ __forceinline__ void mma_f16_zero(float* d, const uint32_t* a, const uint32_t* b) {
    asm volatile(
        "mma.sync.aligned.m16n8k16.row.col.f32.f16.f16.f32 "
        "{%0,%1,%2,%3}, {%4,%5,%6,%7}, {%8,%9}, {%10,%11,%12,%13};"
        : "=f"(d[0]), "=f"(d[1]), "=f"(d[2]), "=f"(d[3])
        : "r"(a[0]), "r"(a[1]), "r"(a[2]), "r"(a[3]), "r"(b[0]), "r"(b[1]),
          "f"(0.0f), "f"(0.0f), "f"(0.0f), "f"(0.0f));
}

// 3-product staged: acc += aS*bB + aB*bS + aB*bB
__device__ __forceinline__ void mma3_staged(float* acc,
                                            const uint32_t* aB, const uint32_t* aS,
                                            const uint32_t* bB, const uint32_t* bS) {
    float tmp[4];
    mma_f16_zero(tmp, aS, bB);
    mma_f16(tmp, aB, bS);
    mma_f16(tmp, aB, bB);
    acc[0] += tmp[0];
    acc[1] += tmp[1];
    acc[2] += tmp[2];
    acc[3] += tmp[3];
}

// ============================================================================
// pack_split: fp32 array -> big/small fp16x2 arrays (one u32 per k-pair)
// ============================================================================
__global__ __launch_bounds__(256)
void pack_split_kernel(const float* __restrict__ X,
                       uint32_t* __restrict__ Xb, uint32_t* __restrict__ Xs,
                       int npairs)
{
    int i = blockIdx.x * 256 + threadIdx.x;
    if (i >= npairs) return;
    float2 v = ((const float2*)X)[i];
    uint32_t b, s;
    split_pack(v.x, v.y, b, s);
    Xb[i] = b;
    Xs[i] = s;
}

// ============================================================================
// rope_pack: RoPE + split-pack in one pass. X: [S, nh*HD] fp32 (proj output);
// writes packed big/small arrays. One thread per (s, h, dd<32): handles the
// even/odd pair (2dd, 2dd+1) and its rotational partners (+64).
// ============================================================================
__global__ __launch_bounds__(256)
void rope_pack_kernel(const float* __restrict__ X,
                      uint32_t* __restrict__ Xb, uint32_t* __restrict__ Xs,
                      int nh, int total)
{
    int idx = blockIdx.x * 256 + threadIdx.x;
    if (idx >= total) return;
    int dd = idx & 31;
    int h  = (idx >> 5) % nh;
    int s  = idx / (32 * nh);
    int d0 = 2 * dd;

    const float* p = X + (long)s * (nh * HD) + h * HD;
    float e0  = (float)(2 * d0)     * (1.0f / 128.0f);
    float e1  = (float)(2 * d0 + 2) * (1.0f / 128.0f);
    float if0 = 1.0f / powf(10000.0f, e0);
    float if1 = 1.0f / powf(10000.0f, e1);
    float a0 = (float)s * if0, a1 = (float)s * if1;
    float c0 = cosf(a0), s0 = sinf(a0);
    float c1 = cosf(a1), s1 = sinf(a1);

    float x10 = p[d0], x11 = p[d0 + 1];
    float x20 = p[d0 + 64], x21 = p[d0 + 65];
    float o0 = x10 * c0 - x20 * s0;       // out[d0]
    float o1 = x11 * c1 - x21 * s1;       // out[d0+1]
    float o2 = x20 * c0 + x10 * s0;       // out[d0+64]
    float o3 = x21 * c1 + x11 * s1;       // out[d0+65]

    long base = ((long)s * (nh * HD) + h * HD) >> 1;  // in k-pairs
    uint32_t b, sm;
    split_pack(o0, o1, b, sm);
    Xb[base + dd] = b;       Xs[base + dd] = sm;
    split_pack(o2, o3, b, sm);
    Xb[base + 32 + dd] = b;  Xs[base + 32 + dd] = sm;
}

// ============================================================================
// fp16x2 3-product GEMM on PRE-PACKED operands: C = alpha * A * B^T
// A,B given as (big, small) u32 k-pair arrays; lda/ldb/strides in k-pairs.
// grid (N/128, M/128, heads). causal=1: skip blocks bx > by.
// ============================================================================
__global__ __launch_bounds__(256)
void gemm_abt3p(const uint32_t* __restrict__ Abp, const uint32_t* __restrict__ Asp,
                const uint32_t* __restrict__ Bbp, const uint32_t* __restrict__ Bsp,
                float* __restrict__ C,
                int Kp, int lda, int ldb, int ldc,
                long aHS, long bHS, long cHS, int bShift,
                float alpha, int causal)
{
    const int h = blockIdx.z;
    Abp += (long)h * aHS;  Asp += (long)h * aHS;
    Bbp += (long)(h >> bShift) * bHS;  Bsp += (long)(h >> bShift) * bHS;
    C   += (long)h * cHS;
    const int bx = blockIdx.x, by = blockIdx.y;
    if (causal && bx > by) return;

    __shared__ uint32_t AsB[8][132];
    __shared__ uint32_t AsS[8][132];
    __shared__ uint32_t BsB[8][132];
    __shared__ uint32_t BsS[8][132];

    const int tid  = threadIdx.x;
    const int lane = tid & 31;
    const int wid  = tid >> 5;
    const int g    = lane >> 2;
    const int tig  = lane & 3;
    const int mbase = (wid >> 2) * 64;
    const int nbase = (wid & 3) * 32;

    const int lrow  = tid >> 2;          // 0..63 (+64)
    const int lcolp = (tid & 3) * 2;     // k-pair offset 0,2,4,6

    const uint32_t* Ab0 = Abp + (long)(by * 128) * lda;
    const uint32_t* As0 = Asp + (long)(by * 128) * lda;
    const uint32_t* Bb0 = Bbp + (long)(bx * 128) * ldb;
    const uint32_t* Bs0 = Bsp + (long)(bx * 128) * ldb;

    float acc[4][4][4];
#pragma unroll
    for (int i = 0; i < 4; i++)
#pragma unroll
        for (int j = 0; j < 4; j++)
#pragma unroll
            for (int k = 0; k < 4; k++) acc[i][j][k] = 0.0f;

    uint2 rab[2], ras[2], rbb[2], rbs[2];
#pragma unroll
    for (int r = 0; r < 2; r++) {
        const int row = lrow + r * 64;
        rab[r] = *(const uint2*)(Ab0 + (long)row * lda + lcolp);
        ras[r] = *(const uint2*)(As0 + (long)row * lda + lcolp);
        rbb[r] = *(const uint2*)(Bb0 + (long)row * ldb + lcolp);
        rbs[r] = *(const uint2*)(Bs0 + (long)row * ldb + lcolp);
    }

    for (int kkp = 0; kkp < Kp; kkp += 8) {
#pragma unroll
        for (int r = 0; r < 2; r++) {
            const int row = lrow + r * 64;
            AsB[lcolp    ][row] = rab[r].x;
            AsB[lcolp + 1][row] = rab[r].y;
            AsS[lcolp    ][row] = ras[r].x;
            AsS[lcolp + 1][row] = ras[r].y;
            BsB[lcolp    ][row] = rbb[r].x;
            BsB[lcolp + 1][row] = rbb[r].y;
            BsS[lcolp    ][row] = rbs[r].x;
            BsS[lcolp + 1][row] = rbs[r].y;
        }
        __syncthreads();

        if (kkp + 8 < Kp) {
#pragma unroll
            for (int r = 0; r < 2; r++) {
                const int row = lrow + r * 64;
                rab[r] = *(const uint2*)(Ab0 + (long)row * lda + kkp + 8 + lcolp);
                ras[r] = *(const uint2*)(As0 + (long)row * lda + kkp + 8 + lcolp);
                rbb[r] = *(const uint2*)(Bb0 + (long)row * ldb + kkp + 8 + lcolp);
                rbs[r] = *(const uint2*)(Bs0 + (long)row * ldb + kkp + 8 + lcolp);
            }
        }

        {
            uint32_t afB[4][4], afS[4][4], bfB[4][2], bfS[4][2];
#pragma unroll
            for (int mt = 0; mt < 4; mt++) {
                const int r0 = mbase + mt * 16 + g;
                afB[mt][0] = AsB[tig    ][r0    ];
                afB[mt][1] = AsB[tig    ][r0 + 8];
                afB[mt][2] = AsB[tig + 4][r0    ];
                afB[mt][3] = AsB[tig + 4][r0 + 8];
                afS[mt][0] = AsS[tig    ][r0    ];
                afS[mt][1] = AsS[tig    ][r0 + 8];
                afS[mt][2] = AsS[tig + 4][r0    ];
                afS[mt][3] = AsS[tig + 4][r0 + 8];
            }
#pragma unroll
            for (int nt = 0; nt < 4; nt++) {
                const int c0 = nbase + nt * 8 + g;
                bfB[nt][0] = BsB[tig    ][c0];
                bfB[nt][1] = BsB[tig + 4][c0];
                bfS[nt][0] = BsS[tig    ][c0];
                bfS[nt][1] = BsS[tig + 4][c0];
            }
#pragma unroll
            for (int mt = 0; mt < 4; mt++)
#pragma unroll
                for (int nt = 0; nt < 4; nt++)
                    mma3_staged(acc[mt][nt], afB[mt], afS[mt], bfB[nt], bfS[nt]);
        }
        __syncthreads();
    }

#pragma unroll
    for (int mt = 0; mt < 4; mt++) {
#pragma unroll
        for (int nt = 0; nt < 4; nt++) {
            const int row0 = by * 128 + mbase + mt * 16 + g;
            const int col0 = bx * 128 + nbase + nt * 8 + 2 * tig;
            C[(long)row0 * ldc + col0    ] = alpha * acc[mt][nt][0];
            C[(long)row0 * ldc + col0 + 1] = alpha * acc[mt][nt][1];
            C[(long)(row0 + 8) * ldc + col0    ] = alpha * acc[mt][nt][2];
            C[(long)(row0 + 8) * ldc + col0 + 1] = alpha * acc[mt][nt][3];
        }
    }
}

// ============================================================================
// Plain fp16 GEMM: C = alpha * A * B^T  (Wv, Wo projections; Output 0 only)
// ============================================================================
__global__ __launch_bounds__(256)
void gemm_abt_f16(const float* __restrict__ A, const float* __restrict__ B,
                  float* __restrict__ C,
                  int K, int lda, int ldb, int ldc, float alpha)
{
    const int bx = blockIdx.x, by = blockIdx.y;

    __shared__ uint32_t As[8][132];
    __shared__ uint32_t Bs[8][132];

    const int tid  = threadIdx.x;
    const int lane = tid & 31;
    const int wid  = tid >> 5;
    const int g    = lane >> 2;
    const int tig  = lane & 3;
    const int mbase = (wid >> 2) * 64;
    const int nbase = (wid & 3) * 32;

    const int lrow = tid >> 2;
    const int lcol = (tid & 3) * 4;
    const int kp0  = lcol >> 1;

    const float* Ab = A + (long)(by * 128) * lda;
    const float* Bb = B + (long)(bx * 128) * ldb;

    float acc[4][4][4];
#pragma unroll
    for (int i = 0; i < 4; i++)
#pragma unroll
        for (int j = 0; j < 4; j++)
#pragma unroll
            for (int k = 0; k < 4; k++) acc[i][j][k] = 0.0f;

    float4 ra[2], rb[2];
#pragma unroll
    for (int r = 0; r < 2; r++) {
        ra[r] = *(const float4*)(Ab + (long)(lrow + r * 64) * lda + lcol);
        rb[r] = *(const float4*)(Bb + (long)(lrow + r * 64) * ldb + lcol);
    }

    for (int kk = 0; kk < K; kk += 16) {
#pragma unroll
        for (int r = 0; r < 2; r++) {
            const int row = lrow + r * 64;
            As[kp0    ][row] = f2h2(ra[r].x, ra[r].y);
            As[kp0 + 1][row] = f2h2(ra[r].z, ra[r].w);
            Bs[kp0    ][row] = f2h2(rb[r].x, rb[r].y);
            Bs[kp0 + 1][row] = f2h2(rb[r].z, rb[r].w);
        }
        __syncthreads();

        if (kk + 16 < K) {
#pragma unroll
            for (int r = 0; r < 2; r++) {
                ra[r] = *(const float4*)(Ab + (long)(lrow + r * 64) * lda + kk + 16 + lcol);
                rb[r] = *(const float4*)(Bb + (long)(lrow + r * 64) * ldb + kk + 16 + lcol);
            }
        }

        {
            uint32_t af[4][4], bf[4][2];
#pragma unroll
            for (int mt = 0; mt < 4; mt++) {
                const int r0 = mbase + mt * 16 + g;
                af[mt][0] = As[tig    ][r0    ];
                af[mt][1] = As[tig    ][r0 + 8];
                af[mt][2] = As[tig + 4][r0    ];
                af[mt][3] = As[tig + 4][r0 + 8];
            }
#pragma unroll
            for (int nt = 0; nt < 4; nt++) {
                const int c0 = nbase + nt * 8 + g;
                bf[nt][0] = Bs[tig    ][c0];
                bf[nt][1] = Bs[tig + 4][c0];
            }
#pragma unroll
            for (int mt = 0; mt < 4; mt++)
#pragma unroll
                for (int nt = 0; nt < 4; nt++)
                    mma_f16(acc[mt][nt], af[mt], bf[nt]);
        }
        __syncthreads();
    }

#pragma unroll
    for (int mt = 0; mt < 4; mt++) {
#pragma unroll
        for (int nt = 0; nt < 4; nt++) {
            const int row0 = by * 128 + mbase + mt * 16 + g;
            const int col0 = bx * 128 + nbase + nt * 8 + 2 * tig;
            C[(long)row0 * ldc + col0    ] = alpha * acc[mt][nt][0];
            C[(long)row0 * ldc + col0 + 1] = alpha * acc[mt][nt][1];
            C[(long)(row0 + 8) * ldc + col0    ] = alpha * acc[mt][nt][2];
            C[(long)(row0 + 8) * ldc + col0 + 1] = alpha * acc[mt][nt][3];
        }
    }
}

// ============================================================================
// Plain fp16 GEMM: C = alpha * A * B  (attn * V, per-head; B row-major K x N)
// causal=1: limit K to (by+1)*128. B packed vertically (k-pairs).
// ============================================================================
__global__ __launch_bounds__(256)
void gemm_ab_f16(const float* __restrict__ A, const float* __restrict__ B,
                 float* __restrict__ C,
                 int K, int lda, int ldb, int ldc,
                 long aHS, long bHS, long cHS, int bShift,
                 float alpha, int causal)
{
    const int h = blockIdx.z;
    A += (long)h * aHS;
    B += (long)(h >> bShift) * bHS;
    C += (long)h * cHS;
    const int bx = blockIdx.x, by = blockIdx.y;

    __shared__ uint32_t As[8][132];
    __shared__ uint32_t Bs[8][132];

    const int tid  = threadIdx.x;
    const int lane = tid & 31;
    const int wid  = tid >> 5;
    const int g    = lane >> 2;
    const int tig  = lane & 3;
    const int mbase = (wid >> 2) * 64;
    const int nbase = (wid & 3) * 32;

    const int lrow  = tid >> 2;
    const int lcol  = (tid & 3) * 4;
    const int kp0   = lcol >> 1;
    const int brow  = tid >> 5;          // k-pair row 0..7
    const int bcol4 = (tid & 31) * 4;

    const float* Ab = A + (long)(by * 128) * lda;

    const int Keff = causal ? (((by + 1) * 128 < K) ? (by + 1) * 128 : K) : K;

    float acc[4][4][4];
#pragma unroll
    for (int i = 0; i < 4; i++)
#pragma unroll
        for (int j = 0; j < 4; j++)
#pragma unroll
            for (int k = 0; k < 4; k++) acc[i][j][k] = 0.0f;

    float4 ra[2], rbl, rbh;
#pragma unroll
    for (int r = 0; r < 2; r++)
        ra[r] = *(const float4*)(Ab + (long)(lrow + r * 64) * lda + lcol);
    rbl = *(const float4*)(B + (long)(2 * brow    ) * ldb + bx * 128 + bcol4);
    rbh = *(const float4*)(B + (long)(2 * brow + 1) * ldb + bx * 128 + bcol4);

    for (int kk = 0; kk < Keff; kk += 16) {
#pragma unroll
        for (int r = 0; r < 2; r++) {
            const int row = lrow + r * 64;
            As[kp0    ][row] = f2h2(ra[r].x, ra[r].y);
            As[kp0 + 1][row] = f2h2(ra[r].z, ra[r].w);
        }
        Bs[brow][bcol4 + 0] = f2h2(rbl.x, rbh.x);
        Bs[brow][bcol4 + 1] = f2h2(rbl.y, rbh.y);
        Bs[brow][bcol4 + 2] = f2h2(rbl.z, rbh.z);
        Bs[brow][bcol4 + 3] = f2h2(rbl.w, rbh.w);
        __syncthreads();

        if (kk + 16 < Keff) {
#pragma unroll
            for (int r = 0; r < 2; r++)
                ra[r] = *(const float4*)(Ab + (long)(lrow + r * 64) * lda + kk + 16 + lcol);
            rbl = *(const float4*)(B + (long)(kk + 16 + 2 * brow    ) * ldb + bx * 128 + bcol4);
            rbh = *(const float4*)(B + (long)(kk + 16 + 2 * brow + 1) * ldb + bx * 128 + bcol4);
        }

        {
            uint32_t af[4][4], bf[4][2];
#pragma unroll
            for (int mt = 0; mt < 4; mt++) {
                const int r0 = mbase + mt * 16 + g;
                af[mt][0] = As[tig    ][r0    ];
                af[mt][1] = As[tig    ][r0 + 8];
                af[mt][2] = As[tig + 4][r0    ];
                af[mt][3] = As[tig + 4][r0 + 8];
            }
#pragma unroll
            for (int nt = 0; nt < 4; nt++) {
                const int c0 = nbase + nt * 8 + g;
                bf[nt][0] = Bs[tig    ][c0];
                bf[nt][1] = Bs[tig + 4][c0];
            }
#pragma unroll
            for (int mt = 0; mt < 4; mt++)
#pragma unroll
                for (int nt = 0; nt < 4; nt++)
                    mma_f16(acc[mt][nt], af[mt], bf[nt]);
        }
        __syncthreads();
    }

#pragma unroll
    for (int mt = 0; mt < 4; mt++) {
#pragma unroll
        for (int nt = 0; nt < 4; nt++) {
            const int row0 = by * 128 + mbase + mt * 16 + g;
            const int col0 = bx * 128 + nbase + nt * 8 + 2 * tig;
            C[(long)row0 * ldc + col0    ] = alpha * acc[mt][nt][0];
            C[(long)row0 * ldc + col0 + 1] = alpha * acc[mt][nt][1];
            C[(long)(row0 + 8) * ldc + col0    ] = alpha * acc[mt][nt][2];
            C[(long)(row0 + 8) * ldc + col0 + 1] = alpha * acc[mt][nt][3];
        }
    }
}

// ============================================================================
// Causal row softmax, online max/sum; zero-fills diagonal block only.
// ============================================================================
__global__ __launch_bounds__(256)
void softmax_causal(float* __restrict__ Sm)
{
    const int q = blockIdx.x, h = blockIdx.y;
    float* row = Sm + ((long)h * S_LEN + q) * S_LEN;
    const int len = q + 1;
    const int tid = threadIdx.x;
    __shared__ float mred[256], sred[256];

    float m = -INFINITY, s = 0.0f;
    for (int i = tid; i < len; i += 256) {
        float x = row[i];
        float nm = fmaxf(m, x);
        s = s * expf(m - nm) + expf(x - nm);
        m = nm;
    }
    mred[tid] = m; sred[tid] = s; __syncthreads();
    for (int st = 128; st > 0; st >>= 1) {
        if (tid < st) {
            float m1 = mred[tid], s1 = sred[tid];
            float m2 = mred[tid + st], s2 = sred[tid + st];
            float nm = fmaxf(m1, m2);
            float sm = 0.0f;
            if (m1 > -INFINITY) sm += s1 * expf(m1 - nm);
            if (m2 > -INFINITY) sm += s2 * expf(m2 - nm);
            mred[tid] = nm; sred[tid] = sm;
        }
        __syncthreads();
    }
    const float M = mred[0];
    const float inv = 1.0f / sred[0];

    for (int i = tid; i < len; i += 256) row[i] = expf(row[i] - M) * inv;

    const int fillEnd = ((q >> 7) + 1) << 7;
    for (int i = len + tid; i < fillEnd; i += 256) row[i] = 0.0f;
}

// ============================================================================
// Column sums: cs[h][k] = sum_q attn[h][q][k] (lower triangle only).
// ============================================================================
__global__ __launch_bounds__(256)
void colsum_kernel(const float* __restrict__ attn, float* __restrict__ cs)
{
    const int k = blockIdx.x * 256 + threadIdx.x;
    const int h = blockIdx.y;
    const float* base = attn + (size_t)h * S_LEN * S_LEN;
    float s = 0.0f;
    for (int q = k; q < S_LEN; q++) s += base[(long)q * S_LEN + k];
    cs[h * S_LEN + k] = s;
}

// ============================================================================
// H2O mask: per head top-HB of colsum[0:SEL] + last RB columns.
// ============================================================================
__global__ __launch_bounds__(256)
void h2o_mask(const float* __restrict__ cs, float* __restrict__ mask)
{
    const int h = blockIdx.x;
    const int tid = threadIdx.x;
    __shared__ float vals[SEL];
    __shared__ float bval[256];
    __shared__ int   bidx[256];

    for (int i = tid; i < SEL; i += 256) vals[i] = cs[h * S_LEN + i];
    float* mrow = mask + h * (S_LEN + 1);
    for (int i = tid; i < S_LEN + 1; i += 256)
        mrow[i] = (i >= (S_LEN + 1 - RB)) ? 1.0f : 0.0f;
    __syncthreads();

    for (int it = 0; it < HB; it++) {
        float best = -INFINITY; int bi = SEL;
        for (int i = tid; i < SEL; i += 256) {
            float v = vals[i];
            if (v > best) { best = v; bi = i; }
        }
        bval[tid] = best; bidx[tid] = bi; __syncthreads();
        for (int s = 128; s > 0; s >>= 1) {
            if (tid < s) {
                if (bval[tid + s] > bval[tid] ||
                    (bval[tid + s] == bval[tid] && bidx[tid + s] < bidx[tid])) {
                    bval[tid] = bval[tid + s];
                    bidx[tid] = bidx[tid + s];
                }
            }
            __syncthreads();
        }
        if (tid == 0) {
            mrow[bidx[0]] = 1.0f;
            vals[bidx[0]] = -INFINITY;
        }
        __syncthreads();
    }
}

// ============================================================================
// Host launcher
// ============================================================================
extern "C" void kernel_launch(void* const* d_in, const int* in_sizes, int n_in,
                              void* d_out, int out_size)
{
    const float* H  = (const float*)d_in[0];
    const float* Wq = (const float*)d_in[1];
    const float* Wk = (const float*)d_in[2];
    const float* Wv = (const float*)d_in[3];
    const float* Wo = (const float*)d_in[4];
    float* out = (float*)d_out;

    float *Q, *K, *V, *Sm, *O, *CS;
    cudaGetSymbolAddress((void**)&Q,  g_Q);
    cudaGetSymbolAddress((void**)&K,  g_K);
    cudaGetSymbolAddress((void**)&V,  g_V);
    cudaGetSymbolAddress((void**)&Sm, g_S);
    cudaGetSymbolAddress((void**)&O,  g_O);
    cudaGetSymbolAddress((void**)&CS, g_CS);

    uint32_t *Hb, *Hs, *Wqb, *Wqs, *Wkb, *Wks, *Qb, *Qs, *Kb, *Ks;
    cudaGetSymbolAddress((void**)&Hb,  g_Hb);
    cudaGetSymbolAddress((void**)&Hs,  g_Hs);
    cudaGetSymbolAddress((void**)&Wqb, g_Wqb);
    cudaGetSymbolAddress((void**)&Wqs, g_Wqs);
    cudaGetSymbolAddress((void**)&Wkb, g_Wkb);
    cudaGetSymbolAddress((void**)&Wks, g_Wks);
    cudaGetSymbolAddress((void**)&Qb,  g_Qb);
    cudaGetSymbolAddress((void**)&Qs,  g_Qs);
    cudaGetSymbolAddress((void**)&Kb,  g_Kb);
    cudaGetSymbolAddress((void**)&Ks,  g_Ks);

    const float inv_sqrt_hd = 0.08838834764831845f; // 1/sqrt(128)

    // Pre-pack mask-path operands (split computed once)
    {
        int npH  = S_LEN * HID / 2;
        int npWq = HID * HID / 2;
        int npWk = NKV * HD * HID / 2;
        pack_split_kernel<<<(npH  + 255) / 256, 256>>>(H,  Hb,  Hs,  npH);
        pack_split_kernel<<<(npWq + 255) / 256, 256>>>(Wq, Wqb, Wqs, npWq);
        pack_split_kernel<<<(npWk + 255) / 256, 256>>>(Wk, Wkb, Wks, npWk);
    }

    // Q, K projections: packed 3-product path (mask-critical)
    gemm_abt3p<<<dim3(HID / 128, S_LEN / 128, 1), 256>>>(
        Hb, Hs, Wqb, Wqs, Q, HID / 2, HID / 2, HID / 2, HID,
        0, 0, 0, 0, 1.0f, 0);
    gemm_abt3p<<<dim3((NKV * HD) / 128, S_LEN / 128, 1), 256>>>(
        Hb, Hs, Wkb, Wks, K, HID / 2, HID / 2, HID / 2, NKV * HD,
        0, 0, 0, 0, 1.0f, 0);
    // V projection: plain fp16 (Output 0 only)
    gemm_abt_f16<<<dim3((NKV * HD) / 128, S_LEN / 128, 1), 256>>>(
        H, Wv, V, HID, HID, HID, NKV * HD, 1.0f);

    // RoPE + pack (split computed once, post-rotation)
    {
        int totQ = S_LEN * NH * 32;
        rope_pack_kernel<<<(totQ + 255) / 256, 256>>>(Q, Qb, Qs, NH, totQ);
        int totK = S_LEN * NKV * 32;
        rope_pack_kernel<<<(totK + 255) / 256, 256>>>(K, Kb, Ks, NKV, totK);
    }

    // scores = Q K^T / sqrt(HD): packed 3-product path
    gemm_abt3p<<<dim3(S_LEN / 128, S_LEN / 128, NH), 256>>>(
        Qb, Qs, Kb, Ks, Sm, HD / 2, HID / 2, (NKV * HD) / 2, S_LEN,
        HD / 2, HD / 2, (long)S_LEN * S_LEN, 2, inv_sqrt_hd, 1);

    // softmax (online; zero-fills diagonal blocks only)
    softmax_causal<<<dim3(S_LEN, NH), 256>>>(Sm);

    // column sums
    colsum_kernel<<<dim3(S_LEN / 256, NH), 256>>>(Sm, CS);

    // context = attn * V : plain fp16
    gemm_ab_f16<<<dim3(HD / 128, S_LEN / 128, NH), 256>>>(
        Sm, V, O, S_LEN, S_LEN, NKV * HD, HID,
        (long)S_LEN * S_LEN, HD, HD, 2, 1.0f, 1);

    // attn_output = O * Wo^T : plain fp16
    gemm_abt_f16<<<dim3(HID / 128, S_LEN / 128, 1), 256>>>(
        O, Wo, out, HID, HID, HID, HID, 1.0f);

    // H2O mask
    {
        size_t maskOff = (size_t)out_size - (size_t)NH * (S_LEN + 1);
        h2o_mask<<<NH, 256>>>(CS, out + maskOff);
    }
}

// round 12
// speedup vs baseline: 1.1145x; 1.1145x over previous
#include <cuda_runtime.h>
#include <cuda_fp16.h>
#include <math.h>
#include <stdint.h>

// ----------------------------------------------------------------------------
// LlamaAttention + H2O mask. fp16 tensor-core GEMMs (m16n8k16):
//   - mask-critical path (Wq, Wk, QK^T): fp16x2 3-product staged split
//     (in-GEMM split, R10-proven). Wq+Wk projections MERGED into one launch
//     (grid z) so Wk's small grid backfills Wq's tail wave.
//   - Output-0-only path (Wv, attn*V, Wo): plain fp16.
// B=1, S=2048, HID=4096, NH=32, NKV=8, HD=128, GROUPS=4, HB=RB=204
// ----------------------------------------------------------------------------

#define S_LEN   2048
#define HID     4096
#define NH      32
#define NKV     8
#define HD      128
#define HB      204
#define RB      204
#define SEL     (S_LEN - RB)   // 1844

__device__ float g_Q [S_LEN * HID];
__device__ float g_K [S_LEN * NKV * HD];
__device__ float g_V [S_LEN * NKV * HD];
__device__ float g_S [(size_t)NH * S_LEN * S_LEN];
__device__ float g_O [S_LEN * HID];
__device__ float g_CS[NH * S_LEN];

// pack two fp32 (consecutive k) into one fp16x2 register (low = even k)
__device__ __forceinline__ uint32_t f2h2(float lo, float hi) {
    __half2 h = __floats2half2_rn(lo, hi);
    return *reinterpret_cast<uint32_t*>(&h);
}

// split-pack: big pair + small (residual) pair
__device__ __forceinline__ void split_pack(float x0, float x1,
                                           uint32_t& bp, uint32_t& sp) {
    __half b0 = __float2half_rn(x0);
    __half b1 = __float2half_rn(x1);
    float r0 = x0 - __half2float(b0);
    float r1 = x1 - __half2float(b1);
    __half2 bb = __halves2half2(b0, b1);
    __half2 ss = __halves2half2(__float2half_rn(r0), __float2half_rn(r1));
    bp = *reinterpret_cast<uint32_t*>(&bb);
    sp = *reinterpret_cast<uint32_t*>(&ss);
}

// D += A*B  (fp16 m16n8k16, fp32 accumulate)
__device__ __forceinline__ void mma_f16(float* c, const uint32_t* a, const uint32_t* b) {
    asm volatile(
        "mma.sync.aligned.m16n8k16.row.col.f32.f16.f16.f32 "
        "{%0,%1,%2,%3}, {%4,%5,%6,%7}, {%8,%9}, {%0,%1,%2,%3};"
        : "+f"(c[0]), "+f"(c[1]), "+f"(c[2]), "+f"(c[3])
        : "r"(a[0]), "r"(a[1]), "r"(a[2]), "r"(a[3]), "r"(b[0]), "r"(b[1]));
}

// D = A*B + 0 (fresh accumulation chain)
__device__ __forceinline__ void mma_f16_zero(float* d, const uint32_t* a, const uint32_t* b) {
    asm volatile(
        "mma.sync.aligned.m16n8k16.row.col.f32.f16.f16.f32 "
        "{%0,%1,%2,%3}, {%4,%5,%6,%7}, {%8,%9}, {%10,%11,%12,%13};"
        : "=f"(d[0]), "=f"(d[1]), "=f"(d[2]), "=f"(d[3])
        : "r"(a[0]), "r"(a[1]), "r"(a[2]), "r"(a[3]), "r"(b[0]), "r"(b[1]),
          "f"(0.0f), "f"(0.0f), "f"(0.0f), "f"(0.0f));
}

// 3-product staged: acc += aS*bB + aB*bS + aB*bB
__device__ __forceinline__ void mma3_staged(float* acc,
                                            const uint32_t* aB, const uint32_t* aS,
                                            const uint32_t* bB, const uint32_t* bS) {
    float tmp[4];
    mma_f16_zero(tmp, aS, bB);
    mma_f16(tmp, aB, bS);
    mma_f16(tmp, aB, bB);
    acc[0] += tmp[0];
    acc[1] += tmp[1];
    acc[2] += tmp[2];
    acc[3] += tmp[3];
}

// ============================================================================
// Shared staged-GEMM body: C = alpha * A * B^T, fp16x2 3-product split.
// A: M x K row-major (lda), B: N x K row-major (ldb), C row-major (ldc).
// ============================================================================
__device__ __forceinline__
void gemm_abt3_body(const float* __restrict__ A, const float* __restrict__ B,
                    float* __restrict__ C,
                    int K, int lda, int ldb, int ldc,
                    int bx, int by, float alpha)
{
    __shared__ uint32_t AsB[8][132];
    __shared__ uint32_t AsS[8][132];
    __shared__ uint32_t BsB[8][132];
    __shared__ uint32_t BsS[8][132];

    const int tid  = threadIdx.x;
    const int lane = tid & 31;
    const int wid  = tid >> 5;
    const int g    = lane >> 2;
    const int tig  = lane & 3;
    const int mbase = (wid >> 2) * 64;
    const int nbase = (wid & 3) * 32;

    const int lrow = tid >> 2;           // 0..63 (+64)
    const int lcol = (tid & 3) * 4;      // k offset 0,4,8,12
    const int kp0  = lcol >> 1;          // k-pair row 0,2,4,6

    const float* Ab = A + (long)(by * 128) * lda;
    const float* Bb = B + (long)(bx * 128) * ldb;

    float acc[4][4][4];
#pragma unroll
    for (int i = 0; i < 4; i++)
#pragma unroll
        for (int j = 0; j < 4; j++)
#pragma unroll
            for (int k = 0; k < 4; k++) acc[i][j][k] = 0.0f;

    float4 ra[2], rb[2];
#pragma unroll
    for (int r = 0; r < 2; r++) {
        ra[r] = *(const float4*)(Ab + (long)(lrow + r * 64) * lda + lcol);
        rb[r] = *(const float4*)(Bb + (long)(lrow + r * 64) * ldb + lcol);
    }

    for (int kk = 0; kk < K; kk += 16) {
#pragma unroll
        for (int r = 0; r < 2; r++) {
            const int row = lrow + r * 64;
            split_pack(ra[r].x, ra[r].y, AsB[kp0    ][row], AsS[kp0    ][row]);
            split_pack(ra[r].z, ra[r].w, AsB[kp0 + 1][row], AsS[kp0 + 1][row]);
            split_pack(rb[r].x, rb[r].y, BsB[kp0    ][row], BsS[kp0    ][row]);
            split_pack(rb[r].z, rb[r].w, BsB[kp0 + 1][row], BsS[kp0 + 1][row]);
        }
        __syncthreads();

        if (kk + 16 < K) {
#pragma unroll
            for (int r = 0; r < 2; r++) {
                ra[r] = *(const float4*)(Ab + (long)(lrow + r * 64) * lda + kk + 16 + lcol);
                rb[r] = *(const float4*)(Bb + (long)(lrow + r * 64) * ldb + kk + 16 + lcol);
            }
        }

        {
            uint32_t afB[4][4], afS[4][4], bfB[4][2], bfS[4][2];
#pragma unroll
            for (int mt = 0; mt < 4; mt++) {
                const int r0 = mbase + mt * 16 + g;
                afB[mt][0] = AsB[tig    ][r0    ];
                afB[mt][1] = AsB[tig    ][r0 + 8];
                afB[mt][2] = AsB[tig + 4][r0    ];
                afB[mt][3] = AsB[tig + 4][r0 + 8];
                afS[mt][0] = AsS[tig    ][r0    ];
                afS[mt][1] = AsS[tig    ][r0 + 8];
                afS[mt][2] = AsS[tig + 4][r0    ];
                afS[mt][3] = AsS[tig + 4][r0 + 8];
            }
#pragma unroll
            for (int nt = 0; nt < 4; nt++) {
                const int c0 = nbase + nt * 8 + g;
                bfB[nt][0] = BsB[tig    ][c0];
                bfB[nt][1] = BsB[tig + 4][c0];
                bfS[nt][0] = BsS[tig    ][c0];
                bfS[nt][1] = BsS[tig + 4][c0];
            }
#pragma unroll
            for (int mt = 0; mt < 4; mt++)
#pragma unroll
                for (int nt = 0; nt < 4; nt++)
                    mma3_staged(acc[mt][nt], afB[mt], afS[mt], bfB[nt], bfS[nt]);
        }
        __syncthreads();
    }

#pragma unroll
    for (int mt = 0; mt < 4; mt++) {
#pragma unroll
        for (int nt = 0; nt < 4; nt++) {
            const int row0 = by * 128 + mbase + mt * 16 + g;
            const int col0 = bx * 128 + nbase + nt * 8 + 2 * tig;
            C[(long)row0 * ldc + col0    ] = alpha * acc[mt][nt][0];
            C[(long)row0 * ldc + col0 + 1] = alpha * acc[mt][nt][1];
            C[(long)(row0 + 8) * ldc + col0    ] = alpha * acc[mt][nt][2];
            C[(long)(row0 + 8) * ldc + col0 + 1] = alpha * acc[mt][nt][3];
        }
    }
}

// ============================================================================
// Merged Q+K projection launch: grid (32, 16, 2).
// z=0: Q = H * Wq^T (bx<32). z=1: K = H * Wk^T (bx<8; others exit).
// Backfills Wq's tail wave with Wk blocks.
// ============================================================================
__global__ __launch_bounds__(256)
void gemm_qk_proj(const float* __restrict__ H_,
                  const float* __restrict__ Wq, const float* __restrict__ Wk,
                  float* __restrict__ Q, float* __restrict__ K_)
{
    const int z = blockIdx.z;
    if (z == 1 && blockIdx.x >= (NKV * HD) / 128) return;
    const float* B = z ? Wk : Wq;
    float*       C = z ? K_ : Q;
    const int  ldc = z ? (NKV * HD) : HID;
    gemm_abt3_body(H_, B, C, HID, HID, HID, ldc,
                   blockIdx.x, blockIdx.y, 1.0f);
}

// ============================================================================
// fp16x2 3-product GEMM: scores = alpha * Q K^T per head (causal).
// ============================================================================
__global__ __launch_bounds__(256)
void gemm_scores3h(const float* __restrict__ Q, const float* __restrict__ K_,
                   float* __restrict__ Sm, float alpha)
{
    const int h = blockIdx.z;
    const int bx = blockIdx.x, by = blockIdx.y;
    if (bx > by) return;
    gemm_abt3_body(Q + (long)h * HD, K_ + (long)(h >> 2) * HD,
                   Sm + (long)h * S_LEN * S_LEN,
                   HD, HID, NKV * HD, S_LEN, bx, by, alpha);
}

// ============================================================================
// Plain fp16 GEMM: C = alpha * A * B^T  (Wv, Wo projections; Output 0 only)
// ============================================================================
__global__ __launch_bounds__(256)
void gemm_abt_f16(const float* __restrict__ A, const float* __restrict__ B,
                  float* __restrict__ C,
                  int K, int lda, int ldb, int ldc, float alpha)
{
    const int bx = blockIdx.x, by = blockIdx.y;

    __shared__ uint32_t As[8][132];
    __shared__ uint32_t Bs[8][132];

    const int tid  = threadIdx.x;
    const int lane = tid & 31;
    const int wid  = tid >> 5;
    const int g    = lane >> 2;
    const int tig  = lane & 3;
    const int mbase = (wid >> 2) * 64;
    const int nbase = (wid & 3) * 32;

    const int lrow = tid >> 2;
    const int lcol = (tid & 3) * 4;
    const int kp0  = lcol >> 1;

    const float* Ab = A + (long)(by * 128) * lda;
    const float* Bb = B + (long)(bx * 128) * ldb;

    float acc[4][4][4];
#pragma unroll
    for (int i = 0; i < 4; i++)
#pragma unroll
        for (int j = 0; j < 4; j++)
#pragma unroll
            for (int k = 0; k < 4; k++) acc[i][j][k] = 0.0f;

    float4 ra[2], rb[2];
#pragma unroll
    for (int r = 0; r < 2; r++) {
        ra[r] = *(const float4*)(Ab + (long)(lrow + r * 64) * lda + lcol);
        rb[r] = *(const float4*)(Bb + (long)(lrow + r * 64) * ldb + lcol);
    }

    for (int kk = 0; kk < K; kk += 16) {
#pragma unroll
        for (int r = 0; r < 2; r++) {
            const int row = lrow + r * 64;
            As[kp0    ][row] = f2h2(ra[r].x, ra[r].y);
            As[kp0 + 1][row] = f2h2(ra[r].z, ra[r].w);
            Bs[kp0    ][row] = f2h2(rb[r].x, rb[r].y);
            Bs[kp0 + 1][row] = f2h2(rb[r].z, rb[r].w);
        }
        __syncthreads();

        if (kk + 16 < K) {
#pragma unroll
            for (int r = 0; r < 2; r++) {
                ra[r] = *(const float4*)(Ab + (long)(lrow + r * 64) * lda + kk + 16 + lcol);
                rb[r] = *(const float4*)(Bb + (long)(lrow + r * 64) * ldb + kk + 16 + lcol);
            }
        }

        {
            uint32_t af[4][4], bf[4][2];
#pragma unroll
            for (int mt = 0; mt < 4; mt++) {
                const int r0 = mbase + mt * 16 + g;
                af[mt][0] = As[tig    ][r0    ];
                af[mt][1] = As[tig    ][r0 + 8];
                af[mt][2] = As[tig + 4][r0    ];
                af[mt][3] = As[tig + 4][r0 + 8];
            }
#pragma unroll
            for (int nt = 0; nt < 4; nt++) {
                const int c0 = nbase + nt * 8 + g;
                bf[nt][0] = Bs[tig    ][c0];
                bf[nt][1] = Bs[tig + 4][c0];
            }
#pragma unroll
            for (int mt = 0; mt < 4; mt++)
#pragma unroll
                for (int nt = 0; nt < 4; nt++)
                    mma_f16(acc[mt][nt], af[mt], bf[nt]);
        }
        __syncthreads();
    }

#pragma unroll
    for (int mt = 0; mt < 4; mt++) {
#pragma unroll
        for (int nt = 0; nt < 4; nt++) {
            const int row0 = by * 128 + mbase + mt * 16 + g;
            const int col0 = bx * 128 + nbase + nt * 8 + 2 * tig;
            C[(long)row0 * ldc + col0    ] = alpha * acc[mt][nt][0];
            C[(long)row0 * ldc + col0 + 1] = alpha * acc[mt][nt][1];
            C[(long)(row0 + 8) * ldc + col0    ] = alpha * acc[mt][nt][2];
            C[(long)(row0 + 8) * ldc + col0 + 1] = alpha * acc[mt][nt][3];
        }
    }
}

// ============================================================================
// Plain fp16 GEMM: C = alpha * A * B  (attn * V, per-head; B row-major K x N)
// causal=1: limit K to (by+1)*128. B packed vertically (k-pairs).
// ============================================================================
__global__ __launch_bounds__(256)
void gemm_ab_f16(const float* __restrict__ A, const float* __restrict__ B,
                 float* __restrict__ C,
                 int K, int lda, int ldb, int ldc,
                 long aHS, long bHS, long cHS, int bShift,
                 float alpha, int causal)
{
    const int h = blockIdx.z;
    A += (long)h * aHS;
    B += (long)(h >> bShift) * bHS;
    C += (long)h * cHS;
    const int bx = blockIdx.x, by = blockIdx.y;

    __shared__ uint32_t As[8][132];
    __shared__ uint32_t Bs[8][132];

    const int tid  = threadIdx.x;
    const int lane = tid & 31;
    const int wid  = tid >> 5;
    const int g    = lane >> 2;
    const int tig  = lane & 3;
    const int mbase = (wid >> 2) * 64;
    const int nbase = (wid & 3) * 32;

    const int lrow  = tid >> 2;
    const int lcol  = (tid & 3) * 4;
    const int kp0   = lcol >> 1;
    const int brow  = tid >> 5;          // k-pair row 0..7
    const int bcol4 = (tid & 31) * 4;

    const float* Ab = A + (long)(by * 128) * lda;

    const int Keff = causal ? (((by + 1) * 128 < K) ? (by + 1) * 128 : K) : K;

    float acc[4][4][4];
#pragma unroll
    for (int i = 0; i < 4; i++)
#pragma unroll
        for (int j = 0; j < 4; j++)
#pragma unroll
            for (int k = 0; k < 4; k++) acc[i][j][k] = 0.0f;

    float4 ra[2], rbl, rbh;
#pragma unroll
    for (int r = 0; r < 2; r++)
        ra[r] = *(const float4*)(Ab + (long)(lrow + r * 64) * lda + lcol);
    rbl = *(const float4*)(B + (long)(2 * brow    ) * ldb + bx * 128 + bcol4);
    rbh = *(const float4*)(B + (long)(2 * brow + 1) * ldb + bx * 128 + bcol4);

    for (int kk = 0; kk < Keff; kk += 16) {
#pragma unroll
        for (int r = 0; r < 2; r++) {
            const int row = lrow + r * 64;
            As[kp0    ][row] = f2h2(ra[r].x, ra[r].y);
            As[kp0 + 1][row] = f2h2(ra[r].z, ra[r].w);
        }
        Bs[brow][bcol4 + 0] = f2h2(rbl.x, rbh.x);
        Bs[brow][bcol4 + 1] = f2h2(rbl.y, rbh.y);
        Bs[brow][bcol4 + 2] = f2h2(rbl.z, rbh.z);
        Bs[brow][bcol4 + 3] = f2h2(rbl.w, rbh.w);
        __syncthreads();

        if (kk + 16 < Keff) {
#pragma unroll
            for (int r = 0; r < 2; r++)
                ra[r] = *(const float4*)(Ab + (long)(lrow + r * 64) * lda + kk + 16 + lcol);
            rbl = *(const float4*)(B + (long)(kk + 16 + 2 * brow    ) * ldb + bx * 128 + bcol4);
            rbh = *(const float4*)(B + (long)(kk + 16 + 2 * brow + 1) * ldb + bx * 128 + bcol4);
        }

        {
            uint32_t af[4][4], bf[4][2];
#pragma unroll
            for (int mt = 0; mt < 4; mt++) {
                const int r0 = mbase + mt * 16 + g;
                af[mt][0] = As[tig    ][r0    ];
                af[mt][1] = As[tig    ][r0 + 8];
                af[mt][2] = As[tig + 4][r0    ];
                af[mt][3] = As[tig + 4][r0 + 8];
            }
#pragma unroll
            for (int nt = 0; nt < 4; nt++) {
                const int c0 = nbase + nt * 8 + g;
                bf[nt][0] = Bs[tig    ][c0];
                bf[nt][1] = Bs[tig + 4][c0];
            }
#pragma unroll
            for (int mt = 0; mt < 4; mt++)
#pragma unroll
                for (int nt = 0; nt < 4; nt++)
                    mma_f16(acc[mt][nt], af[mt], bf[nt]);
        }
        __syncthreads();
    }

#pragma unroll
    for (int mt = 0; mt < 4; mt++) {
#pragma unroll
        for (int nt = 0; nt < 4; nt++) {
            const int row0 = by * 128 + mbase + mt * 16 + g;
            const int col0 = bx * 128 + nbase + nt * 8 + 2 * tig;
            C[(long)row0 * ldc + col0    ] = alpha * acc[mt][nt][0];
            C[(long)row0 * ldc + col0 + 1] = alpha * acc[mt][nt][1];
            C[(long)(row0 + 8) * ldc + col0    ] = alpha * acc[mt][nt][2];
            C[(long)(row0 + 8) * ldc + col0 + 1] = alpha * acc[mt][nt][3];
        }
    }
}

// ============================================================================
// RoPE in place. X: [S, nh*HD]. One thread per (s, h, d<64).
// ============================================================================
__global__ void rope_kernel(float* __restrict__ X, int nh, int total)
{
    int idx = blockIdx.x * blockDim.x + threadIdx.x;
    if (idx >= total) return;
    int d = idx & 63;
    int h = (idx >> 6) % nh;
    int s = idx / (64 * nh);
    float e    = (float)(2 * d) * (1.0f / 128.0f);
    float invf = 1.0f / powf(10000.0f, e);
    float ang  = (float)s * invf;
    float c = cosf(ang), sn = sinf(ang);
    float* p = X + (long)s * (nh * HD) + h * HD;
    float x1 = p[d], x2 = p[d + 64];
    p[d]      = x1 * c - x2 * sn;
    p[d + 64] = x2 * c + x1 * sn;
}

// ============================================================================
// Causal row softmax, online max/sum; zero-fills diagonal block only.
// ============================================================================
__global__ __launch_bounds__(256)
void softmax_causal(float* __restrict__ Sm)
{
    const int q = blockIdx.x, h = blockIdx.y;
    float* row = Sm + ((long)h * S_LEN + q) * S_LEN;
    const int len = q + 1;
    const int tid = threadIdx.x;
    __shared__ float mred[256], sred[256];

    float m = -INFINITY, s = 0.0f;
    for (int i = tid; i < len; i += 256) {
        float x = row[i];
        float nm = fmaxf(m, x);
        s = s * expf(m - nm) + expf(x - nm);
        m = nm;
    }
    mred[tid] = m; sred[tid] = s; __syncthreads();
    for (int st = 128; st > 0; st >>= 1) {
        if (tid < st) {
            float m1 = mred[tid], s1 = sred[tid];
            float m2 = mred[tid + st], s2 = sred[tid + st];
            float nm = fmaxf(m1, m2);
            float sm = 0.0f;
            if (m1 > -INFINITY) sm += s1 * expf(m1 - nm);
            if (m2 > -INFINITY) sm += s2 * expf(m2 - nm);
            mred[tid] = nm; sred[tid] = sm;
        }
        __syncthreads();
    }
    const float M = mred[0];
    const float inv = 1.0f / sred[0];

    for (int i = tid; i < len; i += 256) row[i] = expf(row[i] - M) * inv;

    const int fillEnd = ((q >> 7) + 1) << 7;
    for (int i = len + tid; i < fillEnd; i += 256) row[i] = 0.0f;
}

// ============================================================================
// Column sums: cs[h][k] = sum_q attn[h][q][k] (lower triangle only).
// ============================================================================
__global__ __launch_bounds__(256)
void colsum_kernel(const float* __restrict__ attn, float* __restrict__ cs)
{
    const int k = blockIdx.x * 256 + threadIdx.x;
    const int h = blockIdx.y;
    const float* base = attn + (size_t)h * S_LEN * S_LEN;
    float s = 0.0f;
    for (int q = k; q < S_LEN; q++) s += base[(long)q * S_LEN + k];
    cs[h * S_LEN + k] = s;
}

// ============================================================================
// H2O mask: per head top-HB of colsum[0:SEL] + last RB columns.
// ============================================================================
__global__ __launch_bounds__(256)
void h2o_mask(const float* __restrict__ cs, float* __restrict__ mask)
{
    const int h = blockIdx.x;
    const int tid = threadIdx.x;
    __shared__ float vals[SEL];
    __shared__ float bval[256];
    __shared__ int   bidx[256];

    for (int i = tid; i < SEL; i += 256) vals[i] = cs[h * S_LEN + i];
    float* mrow = mask + h * (S_LEN + 1);
    for (int i = tid; i < S_LEN + 1; i += 256)
        mrow[i] = (i >= (S_LEN + 1 - RB)) ? 1.0f : 0.0f;
    __syncthreads();

    for (int it = 0; it < HB; it++) {
        float best = -INFINITY; int bi = SEL;
        for (int i = tid; i < SEL; i += 256) {
            float v = vals[i];
            if (v > best) { best = v; bi = i; }
        }
        bval[tid] = best; bidx[tid] = bi; __syncthreads();
        for (int s = 128; s > 0; s >>= 1) {
            if (tid < s) {
                if (bval[tid + s] > bval[tid] ||
                    (bval[tid + s] == bval[tid] && bidx[tid + s] < bidx[tid])) {
                    bval[tid] = bval[tid + s];
                    bidx[tid] = bidx[tid + s];
                }
            }
            __syncthreads();
        }
        if (tid == 0) {
            mrow[bidx[0]] = 1.0f;
            vals[bidx[0]] = -INFINITY;
        }
        __syncthreads();
    }
}

// ============================================================================
// Host launcher
// ============================================================================
extern "C" void kernel_launch(void* const* d_in, const int* in_sizes, int n_in,
                              void* d_out, int out_size)
{
    const float* H  = (const float*)d_in[0];
    const float* Wq = (const float*)d_in[1];
    const float* Wk = (const float*)d_in[2];
    const float* Wv = (const float*)d_in[3];
    const float* Wo = (const float*)d_in[4];
    float* out = (float*)d_out;

    float *Q, *K, *V, *Sm, *O, *CS;
    cudaGetSymbolAddress((void**)&Q,  g_Q);
    cudaGetSymbolAddress((void**)&K,  g_K);
    cudaGetSymbolAddress((void**)&V,  g_V);
    cudaGetSymbolAddress((void**)&Sm, g_S);
    cudaGetSymbolAddress((void**)&O,  g_O);
    cudaGetSymbolAddress((void**)&CS, g_CS);

    const float inv_sqrt_hd = 0.08838834764831845f; // 1/sqrt(128)

    // Q + K projections merged (Wk backfills Wq's tail wave)
    gemm_qk_proj<<<dim3(HID / 128, S_LEN / 128, 2), 256>>>(H, Wq, Wk, Q, K);

    // V projection: plain fp16 (Output 0 only)
    gemm_abt_f16<<<dim3((NKV * HD) / 128, S_LEN / 128, 1), 256>>>(
        H, Wv, V, HID, HID, HID, NKV * HD, 1.0f);

    // RoPE
    {
        int totQ = S_LEN * NH * 64;
        rope_kernel<<<(totQ + 255) / 256, 256>>>(Q, NH, totQ);
        int totK = S_LEN * NKV * 64;
        rope_kernel<<<(totK + 255) / 256, 256>>>(K, NKV, totK);
    }

    // scores = Q K^T / sqrt(HD): staged 3-product, causal
    gemm_scores3h<<<dim3(S_LEN / 128, S_LEN / 128, NH), 256>>>(
        Q, K, Sm, inv_sqrt_hd);

    // softmax (online; zero-fills diagonal blocks only)
    softmax_causal<<<dim3(S_LEN, NH), 256>>>(Sm);

    // column sums
    colsum_kernel<<<dim3(S_LEN / 256, NH), 256>>>(Sm, CS);

    // context = attn * V : plain fp16
    gemm_ab_f16<<<dim3(HD / 128, S_LEN / 128, NH), 256>>>(
        Sm, V, O, S_LEN, S_LEN, NKV * HD, HID,
        (long)S_LEN * S_LEN, HD, HD, 2, 1.0f, 1);

    // attn_output = O * Wo^T : plain fp16
    gemm_abt_f16<<<dim3(HID / 128, S_LEN / 128, 1), 256>>>(
        O, Wo, out, HID, HID, HID, HID, 1.0f);

    // H2O mask
    {
        size_t maskOff = (size_t)out_size - (size_t)NH * (S_LEN + 1);
        h2o_mask<<<NH, 256>>>(CS, out + maskOff);
    }
}